// round 3
// baseline (speedup 1.0000x reference)
#include <cuda_runtime.h>
#include <math.h>

#define NN 80000
#define NE 1280000
#define NET (NE + NN)
#define NGR 256
#define SCAN_B ((NN + 255) / 256)

// ---------------- static device scratch ----------------
__device__ int g_deg[NN];
__device__ int g_rowptr[NN + 1];
__device__ int g_cursor[NN];
__device__ int g_col[NET];
__device__ int g_bsum[SCAN_B];
__device__ float g_h[(size_t)NN * 135];
__device__ float g_o[(size_t)NN * 135];
__device__ float4 g_als[NN];
__device__ float4 g_ald[NN];
__device__ unsigned g_pool[NGR * 4];
__device__ int g_nz;

__device__ __forceinline__ unsigned enc(float f) {
    unsigned u = __float_as_uint(f);
    return (u & 0x80000000u) ? ~u : (u | 0x80000000u);
}
__device__ __forceinline__ float dec(unsigned u) {
    return __uint_as_float((u & 0x80000000u) ? (u ^ 0x80000000u) : ~u);
}
__device__ __forceinline__ long long ld_idx(const void* p, long long i, bool is64) {
    if (is64) return ((const long long*)p)[i];
    return (long long)((const int*)p)[i];
}

// ---------------- graph build ----------------
__global__ void k_init() {
    int i = blockIdx.x * blockDim.x + threadIdx.x;
    if (i < NN) g_deg[i] = 1;
    if (i < NGR * 4) g_pool[i] = 0x007FFFFFu; // enc(-inf)
    if (i == 0) { g_nz = 0; g_rowptr[NN] = NET; }
}

__global__ void k_detect(const int* ei32) {
    int lane = threadIdx.x;
    int nz = 0;
    for (int i = lane; i < 512; i += 32)
        if (ei32[2 * i + 1] != 0) nz++;
    #pragma unroll
    for (int o = 16; o; o >>= 1) nz += __shfl_xor_sync(0xffffffffu, nz, o);
    if (lane == 0) g_nz = nz;   // 0 => int64
}

__global__ void k_count(const void* ei) {
    int e = blockIdx.x * blockDim.x + threadIdx.x;
    if (e >= NE) return;
    bool is64 = (g_nz == 0);
    int dst = (int)ld_idx(ei, (long long)NE + e, is64);
    atomicAdd(&g_deg[dst], 1);
}

__global__ void k_bsum() {
    int b = blockIdx.x, t = threadIdx.x;
    int i = b * 256 + t;
    int v = (i < NN) ? g_deg[i] : 0;
    #pragma unroll
    for (int o = 16; o; o >>= 1) v += __shfl_xor_sync(0xffffffffu, v, o);
    __shared__ int ws[8];
    if ((t & 31) == 0) ws[t >> 5] = v;
    __syncthreads();
    if (t < 8) {
        int s = ws[t];
        #pragma unroll
        for (int o = 4; o; o >>= 1) s += __shfl_xor_sync(0xffu, s, o);
        if (t == 0) g_bsum[b] = s;
    }
}

__global__ void k_sbs() {
    __shared__ int sm[512];
    int t = threadIdx.x;
    int v = (t < SCAN_B) ? g_bsum[t] : 0;
    sm[t] = v;
    __syncthreads();
    #pragma unroll
    for (int off = 1; off < 512; off <<= 1) {
        int u = (t >= off) ? sm[t - off] : 0;
        __syncthreads();
        sm[t] += u;
        __syncthreads();
    }
    if (t < SCAN_B) g_bsum[t] = sm[t] - v;
}

__global__ void k_apply() {
    __shared__ int sm[256];
    int b = blockIdx.x, t = threadIdx.x;
    int i = b * 256 + t;
    int v = (i < NN) ? g_deg[i] : 0;
    sm[t] = v;
    __syncthreads();
    #pragma unroll
    for (int off = 1; off < 256; off <<= 1) {
        int u = (t >= off) ? sm[t - off] : 0;
        __syncthreads();
        sm[t] += u;
        __syncthreads();
    }
    if (i < NN) {
        int p = g_bsum[b] + sm[t] - v;
        g_rowptr[i] = p;
        g_cursor[i] = p;
    }
}

__global__ void k_fill(const void* ei) {
    int e = blockIdx.x * blockDim.x + threadIdx.x;
    if (e >= NET) return;
    bool is64 = (g_nz == 0);
    int s, d;
    if (e < NE) {
        s = (int)ld_idx(ei, e, is64);
        d = (int)ld_idx(ei, (long long)NE + e, is64);
    } else {
        s = d = e - NE;
    }
    int pos = atomicAdd(&g_cursor[d], 1);
    g_col[pos] = s;
}

// ---------------- GEMM + fused attention-logit epilogue ----------------
// Y[n,c] = sum_k X[n,k] W[k,c]; then g_als/g_ald[n][h] = sum_c Y[n,h*C+c']*a_{src,dst}
template<int DIN, int DOUT, int NGRP, int JGRP, int H, int C>
__global__ void k_gemm(const float* __restrict__ X, const float* __restrict__ W,
                       float* __restrict__ Y,
                       const float* __restrict__ a_src, const float* __restrict__ a_dst) {
    constexpr int NPB = NGRP * 4;
    constexpr int CPT = (DOUT + JGRP - 1) / JGRP;
    constexpr int P = DIN + 1;
    __shared__ float xs[NPB * P];
    __shared__ float red_s[NPB * H];
    __shared__ float red_d[NPB * H];
    int tid = threadIdx.x;
    int nodeBase = blockIdx.x * NPB;
    for (int i = tid; i < NPB * DIN; i += NGRP * JGRP) {
        int r = i / DIN, c = i - r * DIN;
        xs[r * P + c] = X[(size_t)(nodeBase + r) * DIN + c];
    }
    for (int i = tid; i < NPB * H; i += NGRP * JGRP) { red_s[i] = 0.f; red_d[i] = 0.f; }
    __syncthreads();
    int ng = tid / JGRP;
    int j = tid % JGRP;
    int c0 = j * CPT;
    float acc[4][CPT];
    #pragma unroll
    for (int q = 0; q < 4; q++)
        #pragma unroll
        for (int m = 0; m < CPT; m++) acc[q][m] = 0.f;
    const float* xp = xs + (ng * 4) * P;
    for (int k = 0; k < DIN; k++) {
        float x0 = xp[k], x1 = xp[P + k], x2 = xp[2 * P + k], x3 = xp[3 * P + k];
        #pragma unroll
        for (int m = 0; m < CPT; m++) {
            int c = c0 + m;
            float w = (c < DOUT) ? __ldg(&W[k * DOUT + c]) : 0.f;
            acc[0][m] += x0 * w;
            acc[1][m] += x1 * w;
            acc[2][m] += x2 * w;
            acc[3][m] += x3 * w;
        }
    }
    #pragma unroll
    for (int q = 0; q < 4; q++) {
        int r = ng * 4 + q;
        int n = nodeBase + r;
        float ps[H], pd[H];
        #pragma unroll
        for (int h = 0; h < H; h++) { ps[h] = 0.f; pd[h] = 0.f; }
        #pragma unroll
        for (int m = 0; m < CPT; m++) {
            int c = c0 + m;
            if (c < DOUT) {
                Y[(size_t)n * DOUT + c] = acc[q][m];
                int h = c / C;
                ps[h] += acc[q][m] * __ldg(&a_src[c]);
                pd[h] += acc[q][m] * __ldg(&a_dst[c]);
            }
        }
        #pragma unroll
        for (int h = 0; h < H; h++) {
            if (ps[h] != 0.f || pd[h] != 0.f) {
                atomicAdd(&red_s[r * H + h], ps[h]);
                atomicAdd(&red_d[r * H + h], pd[h]);
            }
        }
    }
    __syncthreads();
    for (int i = tid; i < NPB * H; i += NGRP * JGRP) {
        int r = i / H, h = i - r * H;
        size_t n = nodeBase + r;
        ((float*)g_als)[n * 4 + h] = red_s[i];
        ((float*)g_ald)[n * 4 + h] = red_d[i];
    }
}

// ---------------- edge softmax + aggregate (warp/node, 4-edge-unrolled gather) ----------------
template<int H, int C, bool RELU>
__global__ void k_agg(const float* __restrict__ hfeat,
                      const float* __restrict__ bias,
                      float* __restrict__ out) {
    constexpr int D = H * C;
    constexpr int K = (D + 31) / 32;
    int wid = (blockIdx.x * blockDim.x + threadIdx.x) >> 5;
    if (wid >= NN) return;
    int lane = threadIdx.x & 31;
    int n = wid;
    int beg = g_rowptr[n], end = g_rowptr[n + 1];
    float4 ald4 = g_ald[n];
    float aldv[3] = { ald4.x, ald4.y, ald4.z };

    float acc[K];
    #pragma unroll
    for (int k = 0; k < K; k++) acc[k] = 0.f;
    float ssum[H];
    #pragma unroll
    for (int h = 0; h < H; h++) ssum[h] = 0.f;
    int hid[K];
    #pragma unroll
    for (int k = 0; k < K; k++) hid[k] = (lane + 32 * k) / C;

    for (int base = beg; base < end; base += 32) {
        int cnt = min(32, end - base);
        int s_l = 0;
        float e_l[H];
        #pragma unroll
        for (int h = 0; h < H; h++) e_l[h] = 0.f;
        if (lane < cnt) {
            s_l = g_col[base + lane];
            float4 a = g_als[s_l];
            float av[3] = { a.x, a.y, a.z };
            #pragma unroll
            for (int h = 0; h < H; h++) {
                float al = av[h] + aldv[h];
                al = (al > 0.f) ? al : 0.2f * al;
                e_l[h] = __expf(fminf(al, 80.f));
            }
        }
        #pragma unroll
        for (int h = 0; h < H; h++) ssum[h] += e_l[h];

        int jj = 0;
        // 4-edge unrolled gather: 4*K independent LDGs in flight
        for (; jj + 4 <= cnt; jj += 4) {
            int s0 = __shfl_sync(0xffffffffu, s_l, jj + 0);
            int s1 = __shfl_sync(0xffffffffu, s_l, jj + 1);
            int s2 = __shfl_sync(0xffffffffu, s_l, jj + 2);
            int s3 = __shfl_sync(0xffffffffu, s_l, jj + 3);
            float e0[H], e1[H], e2[H], e3[H];
            #pragma unroll
            for (int h = 0; h < H; h++) {
                e0[h] = __shfl_sync(0xffffffffu, e_l[h], jj + 0);
                e1[h] = __shfl_sync(0xffffffffu, e_l[h], jj + 1);
                e2[h] = __shfl_sync(0xffffffffu, e_l[h], jj + 2);
                e3[h] = __shfl_sync(0xffffffffu, e_l[h], jj + 3);
            }
            const float* p0 = hfeat + (size_t)s0 * D;
            const float* p1 = hfeat + (size_t)s1 * D;
            const float* p2 = hfeat + (size_t)s2 * D;
            const float* p3 = hfeat + (size_t)s3 * D;
            #pragma unroll
            for (int k = 0; k < K; k++) {
                int c = lane + 32 * k;
                if (c < D) {
                    int hk = hid[k];
                    float ev0 = e0[0], ev1 = e1[0], ev2 = e2[0], ev3 = e3[0];
                    if (H > 1 && hk == 1) { ev0 = e0[H > 1 ? 1 : 0]; ev1 = e1[H > 1 ? 1 : 0]; ev2 = e2[H > 1 ? 1 : 0]; ev3 = e3[H > 1 ? 1 : 0]; }
                    if (H > 2 && hk == 2) { ev0 = e0[H > 2 ? 2 : 0]; ev1 = e1[H > 2 ? 2 : 0]; ev2 = e2[H > 2 ? 2 : 0]; ev3 = e3[H > 2 ? 2 : 0]; }
                    float g0 = __ldg(&p0[c]);
                    float g1 = __ldg(&p1[c]);
                    float g2 = __ldg(&p2[c]);
                    float g3 = __ldg(&p3[c]);
                    acc[k] += ev0 * g0;
                    acc[k] += ev1 * g1;
                    acc[k] += ev2 * g2;
                    acc[k] += ev3 * g3;
                }
            }
        }
        for (; jj < cnt; jj++) {
            int s = __shfl_sync(0xffffffffu, s_l, jj);
            float eh[H];
            #pragma unroll
            for (int h = 0; h < H; h++) eh[h] = __shfl_sync(0xffffffffu, e_l[h], jj);
            const float* hs = hfeat + (size_t)s * D;
            #pragma unroll
            for (int k = 0; k < K; k++) {
                int c = lane + 32 * k;
                if (c < D) {
                    int hk = hid[k];
                    float ev = eh[0];
                    if (H > 1 && hk == 1) ev = eh[H > 1 ? 1 : 0];
                    if (H > 2 && hk == 2) ev = eh[H > 2 ? 2 : 0];
                    acc[k] += ev * __ldg(&hs[c]);
                }
            }
        }
    }
    #pragma unroll
    for (int h = 0; h < H; h++)
        #pragma unroll
        for (int o = 16; o; o >>= 1)
            ssum[h] += __shfl_xor_sync(0xffffffffu, ssum[h], o);
    #pragma unroll
    for (int k = 0; k < K; k++) {
        int c = lane + 32 * k;
        if (c < D) {
            float o = acc[k] / (ssum[hid[k]] + 1e-16f) + __ldg(&bias[c]);
            if (RELU) o = fmaxf(o, 0.f);
            out[(size_t)n * D + c] = o;
        }
    }
}

// ---------------- layer-3 agg (D=4) fused with global max pool ----------------
__global__ void k_agg3(const float* __restrict__ hfeat,
                       const float* __restrict__ bias,
                       const void* __restrict__ batch) {
    int wid = (blockIdx.x * blockDim.x + threadIdx.x) >> 5;
    if (wid >= NN) return;
    int lane = threadIdx.x & 31;
    int sub = lane >> 2, c = lane & 3;
    int n = wid;
    int beg = g_rowptr[n], end = g_rowptr[n + 1];
    float aldn = ((const float*)g_ald)[(size_t)n * 4];
    float acc = 0.f, wsum = 0.f;
    for (int e0 = beg; e0 < end; e0 += 8) {
        int e = e0 + sub;
        if (e < end) {
            int s = g_col[e];
            float al = ((const float*)g_als)[(size_t)s * 4] + aldn;
            al = (al > 0.f) ? al : 0.2f * al;
            float w = __expf(fminf(al, 80.f));
            acc += w * __ldg(&hfeat[(size_t)s * 4 + c]);
            wsum += w;
        }
    }
    #pragma unroll
    for (int o = 4; o < 32; o <<= 1) {
        acc += __shfl_xor_sync(0xffffffffu, acc, o);
        wsum += __shfl_xor_sync(0xffffffffu, wsum, o);
    }
    if (lane < 4) {
        float o = acc / (wsum + 1e-16f) + __ldg(&bias[lane]);
        bool is64 = (g_nz == 0);
        int g = (int)ld_idx(batch, n, is64);
        atomicMax(&g_pool[g * 4 + lane], enc(o));
    }
}

__global__ void k_final(float* __restrict__ out) {
    int g = threadIdx.x;
    if (g >= NGR) return;
    float v[4];
    #pragma unroll
    for (int c = 0; c < 4; c++) {
        float f = dec(g_pool[g * 4 + c]);
        if (isinf(f) && f < 0.f) f = -1e9f;
        v[c] = f;
    }
    float m = fmaxf(fmaxf(v[0], v[1]), fmaxf(v[2], v[3]));
    float s = 0.f;
    #pragma unroll
    for (int c = 0; c < 4; c++) s += expf(v[c] - m);
    float lse = m + logf(s);
    #pragma unroll
    for (int c = 0; c < 4; c++) out[g * 4 + c] = v[c] - lse;
}

// ---------------- launch ----------------
extern "C" void kernel_launch(void* const* d_in, const int* in_sizes, int n_in,
                              void* d_out, int out_size) {
    const float* x   = (const float*)d_in[0];
    const void*  ei  = d_in[1];
    const void*  bat = d_in[2];
    const float* W1  = (const float*)d_in[3];
    const float* as1 = (const float*)d_in[4];
    const float* ad1 = (const float*)d_in[5];
    const float* b1  = (const float*)d_in[6];
    const float* W2  = (const float*)d_in[7];
    const float* as2 = (const float*)d_in[8];
    const float* ad2 = (const float*)d_in[9];
    const float* b2  = (const float*)d_in[10];
    const float* W3  = (const float*)d_in[11];
    const float* as3 = (const float*)d_in[12];
    const float* ad3 = (const float*)d_in[13];
    const float* b3  = (const float*)d_in[14];
    float* out = (float*)d_out;

    float *hbuf, *obuf;
    cudaGetSymbolAddress((void**)&hbuf, g_h);
    cudaGetSymbolAddress((void**)&obuf, g_o);

    k_init<<<(NN + 255) / 256, 256>>>();
    k_detect<<<1, 32>>>((const int*)ei);
    k_count<<<(NE + 255) / 256, 256>>>(ei);
    k_bsum<<<SCAN_B, 256>>>();
    k_sbs<<<1, 512>>>();
    k_apply<<<SCAN_B, 256>>>();
    k_fill<<<(NET + 255) / 256, 256>>>(ei);

    // layer 1: 9 -> 3x45
    k_gemm<9, 135, 16, 16, 3, 45><<<NN / 64, 256>>>(x, W1, hbuf, as1, ad1);
    k_agg<3, 45, true><<<NN / 8, 256>>>(hbuf, b1, obuf);

    // layer 2: 135 -> 3x18
    k_gemm<135, 54, 16, 16, 3, 18><<<NN / 64, 256>>>(obuf, W2, hbuf, as2, ad2);
    k_agg<3, 18, true><<<NN / 8, 256>>>(hbuf, b2, obuf);

    // layer 3: 54 -> 1x4
    k_gemm<54, 4, 32, 8, 1, 4><<<NN / 128, 256>>>(obuf, W3, hbuf, as3, ad3);
    k_agg3<<<NN / 8, 256>>>(hbuf, b3, bat);

    k_final<<<1, 256>>>(out);
}

// round 4
// speedup vs baseline: 1.2951x; 1.2951x over previous
#include <cuda_runtime.h>
#include <math.h>

#define NN 80000
#define NE 1280000
#define NET (NE + NN)
#define NGR 256
#define SCAN_B ((NN + 255) / 256)

// ---------------- static device scratch ----------------
__device__ int g_deg[NN];
__device__ int g_rowptr[NN + 1];
__device__ int g_cursor[NN];
__device__ int g_col[NET];
__device__ int g_bsum[SCAN_B];
__device__ float g_h[(size_t)NN * 135];
__device__ float g_o[(size_t)NN * 135];
__device__ float g_xagg[(size_t)NN * 27];
__device__ float g_v[2][3][9];          // [src/dst][head][k]  layer-1 logit vectors
__device__ float4 g_als[NN];
__device__ float4 g_ald[NN];
__device__ unsigned g_pool[NGR * 4];
__device__ int g_nz;

__device__ __forceinline__ unsigned enc(float f) {
    unsigned u = __float_as_uint(f);
    return (u & 0x80000000u) ? ~u : (u | 0x80000000u);
}
__device__ __forceinline__ float dec(unsigned u) {
    return __uint_as_float((u & 0x80000000u) ? (u ^ 0x80000000u) : ~u);
}
__device__ __forceinline__ long long ld_idx(const void* p, long long i, bool is64) {
    if (is64) return ((const long long*)p)[i];
    return (long long)((const int*)p)[i];
}

// ---------------- graph build ----------------
__global__ void k_init(const int* ei32) {
    int i = blockIdx.x * blockDim.x + threadIdx.x;
    if (i < NN) g_deg[i] = 1;
    if (i < NGR * 4) g_pool[i] = 0x007FFFFFu; // enc(-inf)
    if (i == 0) g_rowptr[NN] = NET;
    // int64-vs-int32 sniff (block 0, warp 0)
    if (blockIdx.x == 0 && threadIdx.x < 32) {
        int lane = threadIdx.x;
        int nz = 0;
        for (int j = lane; j < 512; j += 32)
            if (ei32[2 * j + 1] != 0) nz++;
        #pragma unroll
        for (int o = 16; o; o >>= 1) nz += __shfl_xor_sync(0xffffffffu, nz, o);
        if (lane == 0) g_nz = nz;   // 0 => int64
    }
}

__global__ void k_count(const void* ei) {
    int e = blockIdx.x * blockDim.x + threadIdx.x;
    if (e >= NE) return;
    bool is64 = (g_nz == 0);
    int dst = (int)ld_idx(ei, (long long)NE + e, is64);
    atomicAdd(&g_deg[dst], 1);
}

// layer-1 logit vectors: v[side][h][k] = sum_c W1[k,h*45+c] * a[h,c]
__global__ void k_prep(const float* __restrict__ W1,
                       const float* __restrict__ a_src, const float* __restrict__ a_dst) {
    int t = threadIdx.x;
    if (t >= 54) return;
    int side = t / 27, r = t % 27;
    int h = r / 9, k = r % 9;
    const float* a = side ? a_dst : a_src;
    float s = 0.f;
    for (int c = 0; c < 45; c++)
        s += W1[k * 135 + h * 45 + c] * a[h * 45 + c];
    g_v[side][h][k] = s;
}

// layer-1 logits straight from x (9-dim dots)
__global__ void k_alpha_x(const float* __restrict__ x) {
    int n = blockIdx.x * blockDim.x + threadIdx.x;
    if (n >= NN) return;
    float xv[9];
    #pragma unroll
    for (int k = 0; k < 9; k++) xv[k] = x[(size_t)n * 9 + k];
    float s[3], d[3];
    #pragma unroll
    for (int h = 0; h < 3; h++) {
        float ss = 0.f, dd = 0.f;
        #pragma unroll
        for (int k = 0; k < 9; k++) {
            ss += xv[k] * g_v[0][h][k];
            dd += xv[k] * g_v[1][h][k];
        }
        s[h] = ss; d[h] = dd;
    }
    g_als[n] = make_float4(s[0], s[1], s[2], 0.f);
    g_ald[n] = make_float4(d[0], d[1], d[2], 0.f);
}

__global__ void k_bsum() {
    int b = blockIdx.x, t = threadIdx.x;
    int i = b * 256 + t;
    int v = (i < NN) ? g_deg[i] : 0;
    #pragma unroll
    for (int o = 16; o; o >>= 1) v += __shfl_xor_sync(0xffffffffu, v, o);
    __shared__ int ws[8];
    if ((t & 31) == 0) ws[t >> 5] = v;
    __syncthreads();
    if (t < 8) {
        int s = ws[t];
        #pragma unroll
        for (int o = 4; o; o >>= 1) s += __shfl_xor_sync(0xffu, s, o);
        if (t == 0) g_bsum[b] = s;
    }
}

__global__ void k_sbs() {
    __shared__ int sm[512];
    int t = threadIdx.x;
    int v = (t < SCAN_B) ? g_bsum[t] : 0;
    sm[t] = v;
    __syncthreads();
    #pragma unroll
    for (int off = 1; off < 512; off <<= 1) {
        int u = (t >= off) ? sm[t - off] : 0;
        __syncthreads();
        sm[t] += u;
        __syncthreads();
    }
    if (t < SCAN_B) g_bsum[t] = sm[t] - v;
}

__global__ void k_apply() {
    __shared__ int sm[256];
    int b = blockIdx.x, t = threadIdx.x;
    int i = b * 256 + t;
    int v = (i < NN) ? g_deg[i] : 0;
    sm[t] = v;
    __syncthreads();
    #pragma unroll
    for (int off = 1; off < 256; off <<= 1) {
        int u = (t >= off) ? sm[t - off] : 0;
        __syncthreads();
        sm[t] += u;
        __syncthreads();
    }
    if (i < NN) {
        int p = g_bsum[b] + sm[t] - v;
        g_rowptr[i] = p;
        g_cursor[i] = p;
    }
}

__global__ void k_fill(const void* ei) {
    int e = blockIdx.x * blockDim.x + threadIdx.x;
    if (e >= NET) return;
    bool is64 = (g_nz == 0);
    int s, d;
    if (e < NE) {
        s = (int)ld_idx(ei, e, is64);
        d = (int)ld_idx(ei, (long long)NE + e, is64);
    } else {
        s = d = e - NE;
    }
    int pos = atomicAdd(&g_cursor[d], 1);
    g_col[pos] = s;
}

// ---------------- layer-1 aggregation of raw x: xagg[n, h*9+k] ----------------
// warp per node; lanes 0..26 own (h = lane/9, k = lane%9); 4-edge unrolled gather
__global__ void k_aggx(const float* __restrict__ x) {
    int wid = (blockIdx.x * blockDim.x + threadIdx.x) >> 5;
    if (wid >= NN) return;
    int lane = threadIdx.x & 31;
    int n = wid;
    int hh = lane / 9, cc = lane - hh * 9;
    bool act = lane < 27;
    int beg = g_rowptr[n], end = g_rowptr[n + 1];
    float4 ald4 = g_ald[n];
    float aldv[3] = { ald4.x, ald4.y, ald4.z };
    float acc = 0.f;
    float ssum[3] = { 0.f, 0.f, 0.f };

    for (int base = beg; base < end; base += 32) {
        int cnt = min(32, end - base);
        int s_l = 0;
        float e_l[3] = { 0.f, 0.f, 0.f };
        if (lane < cnt) {
            s_l = g_col[base + lane];
            float4 a = g_als[s_l];
            float av[3] = { a.x, a.y, a.z };
            #pragma unroll
            for (int h = 0; h < 3; h++) {
                float al = av[h] + aldv[h];
                al = (al > 0.f) ? al : 0.2f * al;
                e_l[h] = __expf(fminf(al, 80.f));
            }
        }
        #pragma unroll
        for (int h = 0; h < 3; h++) ssum[h] += e_l[h];

        int jj = 0;
        for (; jj + 4 <= cnt; jj += 4) {
            int s0 = __shfl_sync(0xffffffffu, s_l, jj + 0);
            int s1 = __shfl_sync(0xffffffffu, s_l, jj + 1);
            int s2 = __shfl_sync(0xffffffffu, s_l, jj + 2);
            int s3 = __shfl_sync(0xffffffffu, s_l, jj + 3);
            float w0 = __shfl_sync(0xffffffffu, e_l[0], jj + 0);
            float w0b = __shfl_sync(0xffffffffu, e_l[1], jj + 0);
            float w0c = __shfl_sync(0xffffffffu, e_l[2], jj + 0);
            float w1 = __shfl_sync(0xffffffffu, e_l[0], jj + 1);
            float w1b = __shfl_sync(0xffffffffu, e_l[1], jj + 1);
            float w1c = __shfl_sync(0xffffffffu, e_l[2], jj + 1);
            float w2 = __shfl_sync(0xffffffffu, e_l[0], jj + 2);
            float w2b = __shfl_sync(0xffffffffu, e_l[1], jj + 2);
            float w2c = __shfl_sync(0xffffffffu, e_l[2], jj + 2);
            float w3 = __shfl_sync(0xffffffffu, e_l[0], jj + 3);
            float w3b = __shfl_sync(0xffffffffu, e_l[1], jj + 3);
            float w3c = __shfl_sync(0xffffffffu, e_l[2], jj + 3);
            if (act) {
                float x0 = __ldg(&x[(size_t)s0 * 9 + cc]);
                float x1 = __ldg(&x[(size_t)s1 * 9 + cc]);
                float x2 = __ldg(&x[(size_t)s2 * 9 + cc]);
                float x3 = __ldg(&x[(size_t)s3 * 9 + cc]);
                float wa = (hh == 0) ? w0 : (hh == 1) ? w0b : w0c;
                float wb = (hh == 0) ? w1 : (hh == 1) ? w1b : w1c;
                float wc = (hh == 0) ? w2 : (hh == 1) ? w2b : w2c;
                float wd = (hh == 0) ? w3 : (hh == 1) ? w3b : w3c;
                acc += wa * x0;
                acc += wb * x1;
                acc += wc * x2;
                acc += wd * x3;
            }
        }
        for (; jj < cnt; jj++) {
            int s = __shfl_sync(0xffffffffu, s_l, jj);
            float wa0 = __shfl_sync(0xffffffffu, e_l[0], jj);
            float wa1 = __shfl_sync(0xffffffffu, e_l[1], jj);
            float wa2 = __shfl_sync(0xffffffffu, e_l[2], jj);
            if (act) {
                float xv = __ldg(&x[(size_t)s * 9 + cc]);
                float w = (hh == 0) ? wa0 : (hh == 1) ? wa1 : wa2;
                acc += w * xv;
            }
        }
    }
    #pragma unroll
    for (int h = 0; h < 3; h++)
        #pragma unroll
        for (int o = 16; o; o >>= 1)
            ssum[h] += __shfl_xor_sync(0xffffffffu, ssum[h], o);
    if (act)
        g_xagg[(size_t)n * 27 + lane] = acc / (ssum[hh] + 1e-16f);
}

// ---------------- layer-1 dense map: h1[n,c] = relu( xagg[n,h,:]@W1[:,c] + b1[c] ) ----------------
__global__ void k_map1(const float* __restrict__ W1, const float* __restrict__ b1,
                       float* __restrict__ out) {
    long long i = (long long)blockIdx.x * blockDim.x + threadIdx.x;
    if (i >= (long long)NN * 135) return;
    int n = (int)(i / 135), c = (int)(i - (long long)n * 135);
    int h = c / 45;
    const float* xa = g_xagg + (size_t)n * 27 + h * 9;
    float s = 0.f;
    #pragma unroll
    for (int k = 0; k < 9; k++)
        s += xa[k] * __ldg(&W1[k * 135 + c]);
    s += __ldg(&b1[c]);
    out[i] = fmaxf(s, 0.f);
}

// ---------------- dense GEMM (round-2 form, no epilogue fusion) ----------------
template<int DIN, int DOUT, int NGRP, int JGRP>
__global__ void k_gemm(const float* __restrict__ X, const float* __restrict__ W,
                       float* __restrict__ Y) {
    constexpr int NPB = NGRP * 4;
    constexpr int CPT = (DOUT + JGRP - 1) / JGRP;
    constexpr int P = DIN + 1;
    __shared__ float xs[NPB * P];
    int tid = threadIdx.x;
    int nodeBase = blockIdx.x * NPB;
    for (int i = tid; i < NPB * DIN; i += NGRP * JGRP) {
        int r = i / DIN, c = i - r * DIN;
        xs[r * P + c] = X[(size_t)(nodeBase + r) * DIN + c];
    }
    __syncthreads();
    int ng = tid / JGRP;
    int j = tid % JGRP;
    int c0 = j * CPT;
    float acc[4][CPT];
    #pragma unroll
    for (int q = 0; q < 4; q++)
        #pragma unroll
        for (int m = 0; m < CPT; m++) acc[q][m] = 0.f;
    const float* xp = xs + (ng * 4) * P;
    for (int k = 0; k < DIN; k++) {
        float x0 = xp[k], x1 = xp[P + k], x2 = xp[2 * P + k], x3 = xp[3 * P + k];
        #pragma unroll
        for (int m = 0; m < CPT; m++) {
            int c = c0 + m;
            float w = (c < DOUT) ? __ldg(&W[k * DOUT + c]) : 0.f;
            acc[0][m] += x0 * w;
            acc[1][m] += x1 * w;
            acc[2][m] += x2 * w;
            acc[3][m] += x3 * w;
        }
    }
    #pragma unroll
    for (int q = 0; q < 4; q++) {
        int n = nodeBase + ng * 4 + q;
        #pragma unroll
        for (int m = 0; m < CPT; m++) {
            int c = c0 + m;
            if (c < DOUT) Y[(size_t)n * DOUT + c] = acc[q][m];
        }
    }
}

// ---------------- attention logits from features ----------------
template<int H, int C>
__global__ void k_alpha(const float* __restrict__ hfeat,
                        const float* __restrict__ a_src,
                        const float* __restrict__ a_dst) {
    int i = blockIdx.x * blockDim.x + threadIdx.x;
    if (i >= NN * H) return;
    int n = i / H, hh = i - n * H;
    const float* hp = hfeat + (size_t)n * (H * C) + hh * C;
    float s = 0.f, d = 0.f;
    #pragma unroll 4
    for (int c = 0; c < C; c++) {
        float v = hp[c];
        s += v * __ldg(&a_src[hh * C + c]);
        d += v * __ldg(&a_dst[hh * C + c]);
    }
    ((float*)&g_als[n])[hh] = s;
    ((float*)&g_ald[n])[hh] = d;
}

// ---------------- edge softmax + aggregate (round-2 form) ----------------
template<int H, int C, bool RELU>
__global__ void k_agg(const float* __restrict__ hfeat,
                      const float* __restrict__ bias,
                      float* __restrict__ out) {
    constexpr int D = H * C;
    constexpr int K = (D + 31) / 32;
    int wid = (blockIdx.x * blockDim.x + threadIdx.x) >> 5;
    if (wid >= NN) return;
    int lane = threadIdx.x & 31;
    int n = wid;
    int beg = g_rowptr[n], end = g_rowptr[n + 1];
    float4 ald4 = g_ald[n];
    float aldv[3] = { ald4.x, ald4.y, ald4.z };

    float acc[K];
    #pragma unroll
    for (int k = 0; k < K; k++) acc[k] = 0.f;
    float ssum[H];
    #pragma unroll
    for (int h = 0; h < H; h++) ssum[h] = 0.f;
    int hid[K];
    #pragma unroll
    for (int k = 0; k < K; k++) hid[k] = (lane + 32 * k) / C;

    for (int base = beg; base < end; base += 32) {
        int cnt = min(32, end - base);
        int s_l = 0;
        float e_l[H];
        #pragma unroll
        for (int h = 0; h < H; h++) e_l[h] = 0.f;
        if (lane < cnt) {
            s_l = g_col[base + lane];
            float4 a = g_als[s_l];
            float av[3] = { a.x, a.y, a.z };
            #pragma unroll
            for (int h = 0; h < H; h++) {
                float al = av[h] + aldv[h];
                al = (al > 0.f) ? al : 0.2f * al;
                e_l[h] = __expf(fminf(al, 80.f));
            }
        }
        #pragma unroll
        for (int h = 0; h < H; h++) ssum[h] += e_l[h];
        for (int jj = 0; jj < cnt; jj++) {
            int s = __shfl_sync(0xffffffffu, s_l, jj);
            float eh0 = __shfl_sync(0xffffffffu, e_l[0], jj);
            float eh1 = (H > 1) ? __shfl_sync(0xffffffffu, e_l[H > 1 ? 1 : 0], jj) : 0.f;
            float eh2 = (H > 2) ? __shfl_sync(0xffffffffu, e_l[H > 2 ? 2 : 0], jj) : 0.f;
            const float* hs = hfeat + (size_t)s * D;
            #pragma unroll
            for (int k = 0; k < K; k++) {
                int c = lane + 32 * k;
                if (c < D) {
                    float ev = eh0;
                    if (H > 1 && hid[k] == 1) ev = eh1;
                    if (H > 2 && hid[k] == 2) ev = eh2;
                    acc[k] += ev * __ldg(&hs[c]);
                }
            }
        }
    }
    #pragma unroll
    for (int h = 0; h < H; h++)
        #pragma unroll
        for (int o = 16; o; o >>= 1)
            ssum[h] += __shfl_xor_sync(0xffffffffu, ssum[h], o);
    #pragma unroll
    for (int k = 0; k < K; k++) {
        int c = lane + 32 * k;
        if (c < D) {
            float o = acc[k] / (ssum[hid[k]] + 1e-16f) + __ldg(&bias[c]);
            if (RELU) o = fmaxf(o, 0.f);
            out[(size_t)n * D + c] = o;
        }
    }
}

// ---------------- layer-3 agg (D=4) fused with global max pool ----------------
__global__ void k_agg3(const float* __restrict__ hfeat,
                       const float* __restrict__ bias,
                       const void* __restrict__ batch) {
    int wid = (blockIdx.x * blockDim.x + threadIdx.x) >> 5;
    if (wid >= NN) return;
    int lane = threadIdx.x & 31;
    int sub = lane >> 2, c = lane & 3;
    int n = wid;
    int beg = g_rowptr[n], end = g_rowptr[n + 1];
    float aldn = ((const float*)g_ald)[(size_t)n * 4];
    float acc = 0.f, wsum = 0.f;
    for (int e0 = beg; e0 < end; e0 += 8) {
        int e = e0 + sub;
        if (e < end) {
            int s = g_col[e];
            float al = ((const float*)g_als)[(size_t)s * 4] + aldn;
            al = (al > 0.f) ? al : 0.2f * al;
            float w = __expf(fminf(al, 80.f));
            acc += w * __ldg(&hfeat[(size_t)s * 4 + c]);
            wsum += w;
        }
    }
    #pragma unroll
    for (int o = 4; o < 32; o <<= 1) {
        acc += __shfl_xor_sync(0xffffffffu, acc, o);
        wsum += __shfl_xor_sync(0xffffffffu, wsum, o);
    }
    if (lane < 4) {
        float o = acc / (wsum + 1e-16f) + __ldg(&bias[lane]);
        bool is64 = (g_nz == 0);
        int g = (int)ld_idx(batch, n, is64);
        atomicMax(&g_pool[g * 4 + lane], enc(o));
    }
}

__global__ void k_final(float* __restrict__ out) {
    int g = threadIdx.x;
    if (g >= NGR) return;
    float v[4];
    #pragma unroll
    for (int c = 0; c < 4; c++) {
        float f = dec(g_pool[g * 4 + c]);
        if (isinf(f) && f < 0.f) f = -1e9f;
        v[c] = f;
    }
    float m = fmaxf(fmaxf(v[0], v[1]), fmaxf(v[2], v[3]));
    float s = 0.f;
    #pragma unroll
    for (int c = 0; c < 4; c++) s += expf(v[c] - m);
    float lse = m + logf(s);
    #pragma unroll
    for (int c = 0; c < 4; c++) out[g * 4 + c] = v[c] - lse;
}

// ---------------- launch ----------------
extern "C" void kernel_launch(void* const* d_in, const int* in_sizes, int n_in,
                              void* d_out, int out_size) {
    const float* x   = (const float*)d_in[0];
    const void*  ei  = d_in[1];
    const void*  bat = d_in[2];
    const float* W1  = (const float*)d_in[3];
    const float* as1 = (const float*)d_in[4];
    const float* ad1 = (const float*)d_in[5];
    const float* b1  = (const float*)d_in[6];
    const float* W2  = (const float*)d_in[7];
    const float* as2 = (const float*)d_in[8];
    const float* ad2 = (const float*)d_in[9];
    const float* b2  = (const float*)d_in[10];
    const float* W3  = (const float*)d_in[11];
    const float* as3 = (const float*)d_in[12];
    const float* ad3 = (const float*)d_in[13];
    const float* b3  = (const float*)d_in[14];
    float* out = (float*)d_out;

    float *hbuf, *obuf;
    cudaGetSymbolAddress((void**)&hbuf, g_h);
    cudaGetSymbolAddress((void**)&obuf, g_o);

    k_init<<<(NN + 255) / 256, 256>>>((const int*)ei);       // 1
    k_count<<<(NE + 255) / 256, 256>>>(ei);                  // 2
    k_prep<<<1, 64>>>(W1, as1, ad1);                         // 3
    k_alpha_x<<<(NN + 255) / 256, 256>>>(x);                 // 4 (profiled slot)
    k_bsum<<<SCAN_B, 256>>>();                               // 5
    k_sbs<<<1, 512>>>();                                     // 6
    k_apply<<<SCAN_B, 256>>>();                              // 7
    k_fill<<<(NET + 255) / 256, 256>>>(ei);                  // 8

    // layer 1 (restructured): aggregate x, then dense map to 135
    k_aggx<<<NN / 8, 256>>>(x);                              // 9
    k_map1<<<(int)(((long long)NN * 135 + 255) / 256), 256>>>(W1, b1, obuf); // 10

    // layer 2: 135 -> 3x18
    k_gemm<135, 54, 16, 16><<<NN / 64, 256>>>(obuf, W2, hbuf);
    k_alpha<3, 18><<<(NN * 3 + 255) / 256, 256>>>(hbuf, as2, ad2);
    k_agg<3, 18, true><<<NN / 8, 256>>>(hbuf, b2, obuf);

    // layer 3: 54 -> 1x4
    k_gemm<54, 4, 32, 8><<<NN / 128, 256>>>(obuf, W3, hbuf);
    k_alpha<1, 4><<<(NN + 255) / 256, 256>>>(hbuf, as3, ad3);
    k_agg3<<<NN / 8, 256>>>(hbuf, b3, bat);

    k_final<<<1, 256>>>(out);
}

// round 6
// speedup vs baseline: 1.5082x; 1.1646x over previous
#include <cuda_runtime.h>
#include <math.h>

#define NN 80000
#define NE 1280000
#define NET (NE + NN)
#define NGR 256
#define SCAN_B ((NN + 255) / 256)
#define KP 136
#define WPAD 56

// ---------------- static device scratch ----------------
__device__ int g_deg[NN];
__device__ int g_rowptr[NN + 1];
__device__ int g_cursor[NN];
__device__ int g_col[NET];
__device__ int g_bsum[SCAN_B];
__device__ float g_h[(size_t)NN * 135];
__device__ float g_o[(size_t)NN * 135];
__device__ float g_xagg[(size_t)NN * 27];
__device__ float g_v[2][3][9];           // layer-1 logit vectors
__device__ float g_W2p[KP * WPAD];       // padded W2 [136][56]
__device__ float g_als3[NN];
__device__ float g_ald3[NN];
__device__ float4 g_als[NN];
__device__ float4 g_ald[NN];
__device__ unsigned g_pool[NGR * 4];
__device__ int g_nz;

__device__ __forceinline__ unsigned enc(float f) {
    unsigned u = __float_as_uint(f);
    return (u & 0x80000000u) ? ~u : (u | 0x80000000u);
}
__device__ __forceinline__ float dec(unsigned u) {
    return __uint_as_float((u & 0x80000000u) ? (u ^ 0x80000000u) : ~u);
}
__device__ __forceinline__ long long ld_idx(const void* p, long long i, bool is64) {
    if (is64) return ((const long long*)p)[i];
    return (long long)((const int*)p)[i];
}

// ---------------- graph build ----------------
__global__ void k_init(const int* ei32) {
    int i = blockIdx.x * blockDim.x + threadIdx.x;
    if (i < NN) g_deg[i] = 1;
    if (i < NGR * 4) g_pool[i] = 0x007FFFFFu;
    if (i == 0) g_rowptr[NN] = NET;
    if (blockIdx.x == 0 && threadIdx.x < 32) {
        int lane = threadIdx.x;
        int nz = 0;
        for (int j = lane; j < 512; j += 32)
            if (ei32[2 * j + 1] != 0) nz++;
        #pragma unroll
        for (int o = 16; o; o >>= 1) nz += __shfl_xor_sync(0xffffffffu, nz, o);
        if (lane == 0) g_nz = nz;   // 0 => int64
    }
}

__global__ void k_count(const void* ei) {
    int e = blockIdx.x * blockDim.x + threadIdx.x;
    if (e >= NE) return;
    bool is64 = (g_nz == 0);
    int dst = (int)ld_idx(ei, (long long)NE + e, is64);
    atomicAdd(&g_deg[dst], 1);
}

// layer-1 logit vectors: v[side][h][k] = sum_c W1[k,h*45+c]*a[h,c]
__global__ void k_prep(const float* __restrict__ W1,
                       const float* __restrict__ a_src, const float* __restrict__ a_dst) {
    int t = threadIdx.x;
    if (t >= 54) return;
    int side = t / 27, r = t % 27;
    int h = r / 9, k = r % 9;
    const float* a = side ? a_dst : a_src;
    float s = 0.f;
    for (int c = 0; c < 45; c++)
        s += W1[k * 135 + h * 45 + c] * a[h * 45 + c];
    g_v[side][h][k] = s;
}

// pad W2 into [136][56] (zeros beyond 135x54)
__global__ void k_prep2(const float* __restrict__ W2) {
    int i = blockIdx.x * blockDim.x + threadIdx.x;
    if (i >= KP * WPAD) return;
    int k = i / WPAD, c = i - k * WPAD;
    g_W2p[i] = (k < 135 && c < 54) ? W2[k * 54 + c] : 0.f;
}

__global__ void k_alpha_x(const float* __restrict__ x) {
    int n = blockIdx.x * blockDim.x + threadIdx.x;
    if (n >= NN) return;
    float xv[9];
    #pragma unroll
    for (int k = 0; k < 9; k++) xv[k] = x[(size_t)n * 9 + k];
    float s[3], d[3];
    #pragma unroll
    for (int h = 0; h < 3; h++) {
        float ss = 0.f, dd = 0.f;
        #pragma unroll
        for (int k = 0; k < 9; k++) {
            ss += xv[k] * g_v[0][h][k];
            dd += xv[k] * g_v[1][h][k];
        }
        s[h] = ss; d[h] = dd;
    }
    g_als[n] = make_float4(s[0], s[1], s[2], 0.f);
    g_ald[n] = make_float4(d[0], d[1], d[2], 0.f);
}

__global__ void k_bsum() {
    int b = blockIdx.x, t = threadIdx.x;
    int i = b * 256 + t;
    int v = (i < NN) ? g_deg[i] : 0;
    #pragma unroll
    for (int o = 16; o; o >>= 1) v += __shfl_xor_sync(0xffffffffu, v, o);
    __shared__ int ws[8];
    if ((t & 31) == 0) ws[t >> 5] = v;
    __syncthreads();
    if (t < 8) {
        int s = ws[t];
        #pragma unroll
        for (int o = 4; o; o >>= 1) s += __shfl_xor_sync(0xffu, s, o);
        if (t == 0) g_bsum[b] = s;
    }
}

__global__ void k_sbs() {
    __shared__ int sm[512];
    int t = threadIdx.x;
    int v = (t < SCAN_B) ? g_bsum[t] : 0;
    sm[t] = v;
    __syncthreads();
    #pragma unroll
    for (int off = 1; off < 512; off <<= 1) {
        int u = (t >= off) ? sm[t - off] : 0;
        __syncthreads();
        sm[t] += u;
        __syncthreads();
    }
    if (t < SCAN_B) g_bsum[t] = sm[t] - v;
}

__global__ void k_apply() {
    __shared__ int sm[256];
    int b = blockIdx.x, t = threadIdx.x;
    int i = b * 256 + t;
    int v = (i < NN) ? g_deg[i] : 0;
    sm[t] = v;
    __syncthreads();
    #pragma unroll
    for (int off = 1; off < 256; off <<= 1) {
        int u = (t >= off) ? sm[t - off] : 0;
        __syncthreads();
        sm[t] += u;
        __syncthreads();
    }
    if (i < NN) {
        int p = g_bsum[b] + sm[t] - v;
        g_rowptr[i] = p;
        g_cursor[i] = p;
    }
}

__global__ void k_fill(const void* ei) {
    int e = blockIdx.x * blockDim.x + threadIdx.x;
    if (e >= NET) return;
    bool is64 = (g_nz == 0);
    int s, d;
    if (e < NE) {
        s = (int)ld_idx(ei, e, is64);
        d = (int)ld_idx(ei, (long long)NE + e, is64);
    } else {
        s = d = e - NE;
    }
    int pos = atomicAdd(&g_cursor[d], 1);
    g_col[pos] = s;
}

// ---------------- layer-1: aggregate raw x (27 accumulators), warp/node ----------------
__global__ void k_aggx(const float* __restrict__ x) {
    int wid = (blockIdx.x * blockDim.x + threadIdx.x) >> 5;
    if (wid >= NN) return;
    int lane = threadIdx.x & 31;
    int n = wid;
    int hh = lane / 9, cc = lane - hh * 9;
    bool act = lane < 27;
    int beg = g_rowptr[n], end = g_rowptr[n + 1];
    float4 ald4 = g_ald[n];
    float aldv[3] = { ald4.x, ald4.y, ald4.z };
    float acc = 0.f;
    float ssum[3] = { 0.f, 0.f, 0.f };

    for (int base = beg; base < end; base += 32) {
        int cnt = min(32, end - base);
        int s_l = 0;
        float e_l[3] = { 0.f, 0.f, 0.f };
        if (lane < cnt) {
            s_l = g_col[base + lane];
            float4 a = g_als[s_l];
            float av[3] = { a.x, a.y, a.z };
            #pragma unroll
            for (int h = 0; h < 3; h++) {
                float al = av[h] + aldv[h];
                al = (al > 0.f) ? al : 0.2f * al;
                e_l[h] = __expf(fminf(al, 80.f));
            }
        }
        #pragma unroll
        for (int h = 0; h < 3; h++) ssum[h] += e_l[h];

        int jj = 0;
        for (; jj + 4 <= cnt; jj += 4) {
            int s0 = __shfl_sync(0xffffffffu, s_l, jj + 0);
            int s1 = __shfl_sync(0xffffffffu, s_l, jj + 1);
            int s2 = __shfl_sync(0xffffffffu, s_l, jj + 2);
            int s3 = __shfl_sync(0xffffffffu, s_l, jj + 3);
            float w0a = __shfl_sync(0xffffffffu, e_l[0], jj + 0);
            float w0b = __shfl_sync(0xffffffffu, e_l[1], jj + 0);
            float w0c = __shfl_sync(0xffffffffu, e_l[2], jj + 0);
            float w1a = __shfl_sync(0xffffffffu, e_l[0], jj + 1);
            float w1b = __shfl_sync(0xffffffffu, e_l[1], jj + 1);
            float w1c = __shfl_sync(0xffffffffu, e_l[2], jj + 1);
            float w2a = __shfl_sync(0xffffffffu, e_l[0], jj + 2);
            float w2b = __shfl_sync(0xffffffffu, e_l[1], jj + 2);
            float w2c = __shfl_sync(0xffffffffu, e_l[2], jj + 2);
            float w3a = __shfl_sync(0xffffffffu, e_l[0], jj + 3);
            float w3b = __shfl_sync(0xffffffffu, e_l[1], jj + 3);
            float w3c = __shfl_sync(0xffffffffu, e_l[2], jj + 3);
            if (act) {
                float x0 = __ldg(&x[(size_t)s0 * 9 + cc]);
                float x1 = __ldg(&x[(size_t)s1 * 9 + cc]);
                float x2 = __ldg(&x[(size_t)s2 * 9 + cc]);
                float x3 = __ldg(&x[(size_t)s3 * 9 + cc]);
                float wa = (hh == 0) ? w0a : (hh == 1) ? w0b : w0c;
                float wb = (hh == 0) ? w1a : (hh == 1) ? w1b : w1c;
                float wc = (hh == 0) ? w2a : (hh == 1) ? w2b : w2c;
                float wd = (hh == 0) ? w3a : (hh == 1) ? w3b : w3c;
                acc += wa * x0;
                acc += wb * x1;
                acc += wc * x2;
                acc += wd * x3;
            }
        }
        for (; jj < cnt; jj++) {
            int s = __shfl_sync(0xffffffffu, s_l, jj);
            float wa0 = __shfl_sync(0xffffffffu, e_l[0], jj);
            float wa1 = __shfl_sync(0xffffffffu, e_l[1], jj);
            float wa2 = __shfl_sync(0xffffffffu, e_l[2], jj);
            if (act) {
                float xv = __ldg(&x[(size_t)s * 9 + cc]);
                float w = (hh == 0) ? wa0 : (hh == 1) ? wa1 : wa2;
                acc += w * xv;
            }
        }
    }
    #pragma unroll
    for (int h = 0; h < 3; h++)
        #pragma unroll
        for (int o = 16; o; o >>= 1)
            ssum[h] += __shfl_xor_sync(0xffffffffu, ssum[h], o);
    if (act)
        g_xagg[(size_t)n * 27 + lane] = acc / (ssum[hh] + 1e-16f);
}

// layer-1 dense map: o1[n,c] = relu( xagg[n,h,:]@W1[:,c] + b1 )
__global__ void k_map1(const float* __restrict__ W1, const float* __restrict__ b1,
                       float* __restrict__ out) {
    long long i = (long long)blockIdx.x * blockDim.x + threadIdx.x;
    if (i >= (long long)NN * 135) return;
    int n = (int)(i / 135), c = (int)(i - (long long)n * 135);
    int h = c / 45;
    const float* xa = g_xagg + (size_t)n * 27 + h * 9;
    float s = 0.f;
    #pragma unroll
    for (int k = 0; k < 9; k++)
        s += xa[k] * __ldg(&W1[k * 135 + c]);
    s += __ldg(&b1[c]);
    out[i] = fmaxf(s, 0.f);
}

// ---------------- gemm2: 135 -> 54, vectorized, fused alpha2 epilogue ----------------
__global__ void k_gemm2(const float* __restrict__ X, float* __restrict__ Y,
                        const float* __restrict__ a_src, const float* __restrict__ a_dst) {
    constexpr int NPB = 64;
    __shared__ __align__(16) float xs[NPB * KP];
    int tid = threadIdx.x;
    int nodeBase = blockIdx.x * NPB;
    for (int i = tid; i < NPB * KP; i += 256) {
        int r = i / KP, c = i - r * KP;
        xs[i] = (c < 135) ? X[(size_t)(nodeBase + r) * 135 + c] : 0.f;
    }
    __syncthreads();
    int ng = tid / 16, j = tid & 15;
    int c0 = j * 4;
    float acc[4][4];
    #pragma unroll
    for (int q = 0; q < 4; q++)
        #pragma unroll
        for (int m = 0; m < 4; m++) acc[q][m] = 0.f;
    const float* xp = xs + (ng * 4) * KP;
    for (int k4 = 0; k4 < KP / 4; k4++) {
        float xr0[4], xr1[4], xr2[4], xr3[4];
        *(float4*)xr0 = *(const float4*)&xp[k4 * 4];
        *(float4*)xr1 = *(const float4*)&xp[KP + k4 * 4];
        *(float4*)xr2 = *(const float4*)&xp[2 * KP + k4 * 4];
        *(float4*)xr3 = *(const float4*)&xp[3 * KP + k4 * 4];
        #pragma unroll
        for (int kk = 0; kk < 4; kk++) {
            float wr[4];
            *(float4*)wr = __ldg((const float4*)&g_W2p[(k4 * 4 + kk) * WPAD + c0]);
            #pragma unroll
            for (int m = 0; m < 4; m++) {
                acc[0][m] += xr0[kk] * wr[m];
                acc[1][m] += xr1[kk] * wr[m];
                acc[2][m] += xr2[kk] * wr[m];
                acc[3][m] += xr3[kk] * wr[m];
            }
        }
    }
    // epilogue: store Y + fused logits (half-warp shfl reduction, no atomics)
    float as_c[4], ad_c[4];
    #pragma unroll
    for (int m = 0; m < 4; m++) {
        int c = c0 + m;
        as_c[m] = (c < 54) ? __ldg(&a_src[c]) : 0.f;
        ad_c[m] = (c < 54) ? __ldg(&a_dst[c]) : 0.f;
    }
    #pragma unroll
    for (int q = 0; q < 4; q++) {
        int n = nodeBase + ng * 4 + q;
        float ps0 = 0.f, ps1 = 0.f, ps2 = 0.f;
        float pd0 = 0.f, pd1 = 0.f, pd2 = 0.f;
        #pragma unroll
        for (int m = 0; m < 4; m++) {
            int c = c0 + m;
            if (c < 54) {
                Y[(size_t)n * 54 + c] = acc[q][m];
                int h = c / 18;
                float vs = acc[q][m] * as_c[m];
                float vd = acc[q][m] * ad_c[m];
                if (h == 0) { ps0 += vs; pd0 += vd; }
                else if (h == 1) { ps1 += vs; pd1 += vd; }
                else { ps2 += vs; pd2 += vd; }
            }
        }
        #pragma unroll
        for (int o = 8; o; o >>= 1) {
            ps0 += __shfl_xor_sync(0xffffffffu, ps0, o);
            ps1 += __shfl_xor_sync(0xffffffffu, ps1, o);
            ps2 += __shfl_xor_sync(0xffffffffu, ps2, o);
            pd0 += __shfl_xor_sync(0xffffffffu, pd0, o);
            pd1 += __shfl_xor_sync(0xffffffffu, pd1, o);
            pd2 += __shfl_xor_sync(0xffffffffu, pd2, o);
        }
        if (j == 0) {
            g_als[n] = make_float4(ps0, ps1, ps2, 0.f);
            g_ald[n] = make_float4(pd0, pd1, pd2, 0.f);
        }
    }
}

// ---------------- agg2: layer-2 softmax-aggregate + fused gemm3 + layer-3 logits ----------------
// warp/node; lanes 0..26 own channel pair (2l, 2l+1); head = l/9
__global__ void k_agg2(const float* __restrict__ hfeat,
                       const float* __restrict__ bias,
                       const float* __restrict__ W3,
                       const float* __restrict__ as3, const float* __restrict__ ad3,
                       float* __restrict__ h3out) {
    int wid = (blockIdx.x * blockDim.x + threadIdx.x) >> 5;
    if (wid >= NN) return;
    int lane = threadIdx.x & 31;
    int n = wid;
    bool act = lane < 27;
    int c0 = 2 * lane;
    int hd = lane / 9;
    int beg = g_rowptr[n], end = g_rowptr[n + 1];
    float4 ald4 = g_ald[n];
    float aldv[3] = { ald4.x, ald4.y, ald4.z };
    float2 acc = make_float2(0.f, 0.f);
    float ssum0 = 0.f, ssum1 = 0.f, ssum2 = 0.f;

    for (int base = beg; base < end; base += 32) {
        int cnt = min(32, end - base);
        int s_l = 0;
        float e_l[3] = { 0.f, 0.f, 0.f };
        if (lane < cnt) {
            s_l = g_col[base + lane];
            float4 a = g_als[s_l];
            float av[3] = { a.x, a.y, a.z };
            #pragma unroll
            for (int h = 0; h < 3; h++) {
                float al = av[h] + aldv[h];
                al = (al > 0.f) ? al : 0.2f * al;
                e_l[h] = __expf(fminf(al, 80.f));
            }
        }
        ssum0 += e_l[0]; ssum1 += e_l[1]; ssum2 += e_l[2];

        int jj = 0;
        for (; jj + 4 <= cnt; jj += 4) {
            int s0 = __shfl_sync(0xffffffffu, s_l, jj + 0);
            int s1 = __shfl_sync(0xffffffffu, s_l, jj + 1);
            int s2 = __shfl_sync(0xffffffffu, s_l, jj + 2);
            int s3 = __shfl_sync(0xffffffffu, s_l, jj + 3);
            float w0a = __shfl_sync(0xffffffffu, e_l[0], jj + 0);
            float w0b = __shfl_sync(0xffffffffu, e_l[1], jj + 0);
            float w0c = __shfl_sync(0xffffffffu, e_l[2], jj + 0);
            float w1a = __shfl_sync(0xffffffffu, e_l[0], jj + 1);
            float w1b = __shfl_sync(0xffffffffu, e_l[1], jj + 1);
            float w1c = __shfl_sync(0xffffffffu, e_l[2], jj + 1);
            float w2a = __shfl_sync(0xffffffffu, e_l[0], jj + 2);
            float w2b = __shfl_sync(0xffffffffu, e_l[1], jj + 2);
            float w2c = __shfl_sync(0xffffffffu, e_l[2], jj + 2);
            float w3a = __shfl_sync(0xffffffffu, e_l[0], jj + 3);
            float w3b = __shfl_sync(0xffffffffu, e_l[1], jj + 3);
            float w3c = __shfl_sync(0xffffffffu, e_l[2], jj + 3);
            if (act) {
                float2 g0 = *(const float2*)&hfeat[(size_t)s0 * 54 + c0];
                float2 g1 = *(const float2*)&hfeat[(size_t)s1 * 54 + c0];
                float2 g2 = *(const float2*)&hfeat[(size_t)s2 * 54 + c0];
                float2 g3 = *(const float2*)&hfeat[(size_t)s3 * 54 + c0];
                float wa = (hd == 0) ? w0a : (hd == 1) ? w0b : w0c;
                float wb = (hd == 0) ? w1a : (hd == 1) ? w1b : w1c;
                float wc = (hd == 0) ? w2a : (hd == 1) ? w2b : w2c;
                float wd = (hd == 0) ? w3a : (hd == 1) ? w3b : w3c;
                acc.x += wa * g0.x; acc.y += wa * g0.y;
                acc.x += wb * g1.x; acc.y += wb * g1.y;
                acc.x += wc * g2.x; acc.y += wc * g2.y;
                acc.x += wd * g3.x; acc.y += wd * g3.y;
            }
        }
        for (; jj < cnt; jj++) {
            int s = __shfl_sync(0xffffffffu, s_l, jj);
            float wa0 = __shfl_sync(0xffffffffu, e_l[0], jj);
            float wa1 = __shfl_sync(0xffffffffu, e_l[1], jj);
            float wa2 = __shfl_sync(0xffffffffu, e_l[2], jj);
            if (act) {
                float2 g = *(const float2*)&hfeat[(size_t)s * 54 + c0];
                float w = (hd == 0) ? wa0 : (hd == 1) ? wa1 : wa2;
                acc.x += w * g.x; acc.y += w * g.y;
            }
        }
    }
    #pragma unroll
    for (int o = 16; o; o >>= 1) {
        ssum0 += __shfl_xor_sync(0xffffffffu, ssum0, o);
        ssum1 += __shfl_xor_sync(0xffffffffu, ssum1, o);
        ssum2 += __shfl_xor_sync(0xffffffffu, ssum2, o);
    }
    // o2 = relu(acc/sum + bias)
    float2 o2 = make_float2(0.f, 0.f);
    if (act) {
        float ss = (hd == 0) ? ssum0 : (hd == 1) ? ssum1 : ssum2;
        float inv = 1.f / (ss + 1e-16f);
        o2.x = fmaxf(acc.x * inv + __ldg(&bias[c0]), 0.f);
        o2.y = fmaxf(acc.y * inv + __ldg(&bias[c0 + 1]), 0.f);
    }
    // fused gemm3: h3[m] = sum_c o2[c] * W3[c][m]
    float t0 = 0.f, t1 = 0.f, t2 = 0.f, t3 = 0.f;
    if (act) {
        float4 wr0 = __ldg((const float4*)&W3[c0 * 4]);
        float4 wr1 = __ldg((const float4*)&W3[(c0 + 1) * 4]);
        t0 = o2.x * wr0.x + o2.y * wr1.x;
        t1 = o2.x * wr0.y + o2.y * wr1.y;
        t2 = o2.x * wr0.z + o2.y * wr1.z;
        t3 = o2.x * wr0.w + o2.y * wr1.w;
    }
    #pragma unroll
    for (int o = 16; o; o >>= 1) {
        t0 += __shfl_xor_sync(0xffffffffu, t0, o);
        t1 += __shfl_xor_sync(0xffffffffu, t1, o);
        t2 += __shfl_xor_sync(0xffffffffu, t2, o);
        t3 += __shfl_xor_sync(0xffffffffu, t3, o);
    }
    if (lane == 0) {
        *(float4*)&h3out[(size_t)n * 4] = make_float4(t0, t1, t2, t3);
        g_als3[n] = t0 * __ldg(&as3[0]) + t1 * __ldg(&as3[1]) + t2 * __ldg(&as3[2]) + t3 * __ldg(&as3[3]);
        g_ald3[n] = t0 * __ldg(&ad3[0]) + t1 * __ldg(&ad3[1]) + t2 * __ldg(&ad3[2]) + t3 * __ldg(&ad3[3]);
    }
}

// ---------------- layer-3 agg (D=4) fused with global max pool ----------------
__global__ void k_agg3(const float* __restrict__ hfeat,
                       const float* __restrict__ bias,
                       const void* __restrict__ batch) {
    int wid = (blockIdx.x * blockDim.x + threadIdx.x) >> 5;
    if (wid >= NN) return;
    int lane = threadIdx.x & 31;
    int sub = lane >> 2, c = lane & 3;
    int n = wid;
    int beg = g_rowptr[n], end = g_rowptr[n + 1];
    float aldn = g_ald3[n];
    float acc = 0.f, wsum = 0.f;
    for (int e0 = beg; e0 < end; e0 += 8) {
        int e = e0 + sub;
        if (e < end) {
            int s = g_col[e];
            float al = g_als3[s] + aldn;
            al = (al > 0.f) ? al : 0.2f * al;
            float w = __expf(fminf(al, 80.f));
            acc += w * __ldg(&hfeat[(size_t)s * 4 + c]);
            wsum += w;
        }
    }
    #pragma unroll
    for (int o = 4; o < 32; o <<= 1) {
        acc += __shfl_xor_sync(0xffffffffu, acc, o);
        wsum += __shfl_xor_sync(0xffffffffu, wsum, o);
    }
    if (lane < 4) {
        float o = acc / (wsum + 1e-16f) + __ldg(&bias[lane]);
        bool is64 = (g_nz == 0);
        int g = (int)ld_idx(batch, n, is64);
        atomicMax(&g_pool[g * 4 + lane], enc(o));
    }
}

__global__ void k_final(float* __restrict__ out) {
    int g = threadIdx.x;
    if (g >= NGR) return;
    float v[4];
    #pragma unroll
    for (int c = 0; c < 4; c++) {
        float f = dec(g_pool[g * 4 + c]);
        if (isinf(f) && f < 0.f) f = -1e9f;
        v[c] = f;
    }
    float m = fmaxf(fmaxf(v[0], v[1]), fmaxf(v[2], v[3]));
    float s = 0.f;
    #pragma unroll
    for (int c = 0; c < 4; c++) s += expf(v[c] - m);
    float lse = m + logf(s);
    #pragma unroll
    for (int c = 0; c < 4; c++) out[g * 4 + c] = v[c] - lse;
}

// ---------------- launch ----------------
extern "C" void kernel_launch(void* const* d_in, const int* in_sizes, int n_in,
                              void* d_out, int out_size) {
    const float* x   = (const float*)d_in[0];
    const void*  ei  = d_in[1];
    const void*  bat = d_in[2];
    const float* W1  = (const float*)d_in[3];
    const float* as1 = (const float*)d_in[4];
    const float* ad1 = (const float*)d_in[5];
    const float* b1  = (const float*)d_in[6];
    const float* W2  = (const float*)d_in[7];
    const float* as2 = (const float*)d_in[8];
    const float* ad2 = (const float*)d_in[9];
    const float* b2  = (const float*)d_in[10];
    const float* W3  = (const float*)d_in[11];
    const float* as3 = (const float*)d_in[12];
    const float* ad3 = (const float*)d_in[13];
    const float* b3  = (const float*)d_in[14];
    float* out = (float*)d_out;

    float *hbuf, *obuf;
    cudaGetSymbolAddress((void**)&hbuf, g_h);
    cudaGetSymbolAddress((void**)&obuf, g_o);

    k_init<<<(NN + 255) / 256, 256>>>((const int*)ei);
    k_count<<<(NE + 255) / 256, 256>>>(ei);
    k_prep<<<1, 64>>>(W1, as1, ad1);
    k_alpha_x<<<(NN + 255) / 256, 256>>>(x);
    k_prep2<<<(KP * WPAD + 255) / 256, 256>>>(W2);
    k_bsum<<<SCAN_B, 256>>>();
    k_sbs<<<1, 512>>>();
    k_apply<<<SCAN_B, 256>>>();
    k_fill<<<(NET + 255) / 256, 256>>>(ei);

    // layer 1: aggregate x, then dense map to 135
    k_aggx<<<NN / 8, 256>>>(x);
    k_map1<<<(int)(((long long)NN * 135 + 255) / 256), 256>>>(W1, b1, obuf);

    // layer 2 GEMM (fused alpha2) -> agg2 (fused gemm3 + alpha3, h3 -> obuf)
    k_gemm2<<<NN / 64, 256>>>(obuf, hbuf, as2, ad2);
    k_agg2<<<NN / 8, 256>>>(hbuf, b2, W3, as3, ad3, obuf);

    // layer 3 aggregate + pool
    k_agg3<<<NN / 8, 256>>>(obuf, b3, bat);

    k_final<<<1, 256>>>(out);
}

// round 7
// speedup vs baseline: 1.6610x; 1.1013x over previous
#include <cuda_runtime.h>
#include <math.h>

#define NN 80000
#define NE 1280000
#define NET (NE + NN)
#define NGR 256
#define NB5 157          // ceil(NN/512)
#define KP 136
#define WPAD 56

// ---------------- static device scratch (zero at entry, restored at exit) ----------------
__device__ int g_deg[NN];          // ZERO at entry (restored by k_final)
__device__ int g_rowptr[NN + 1];
__device__ int g_cursor[NN];
__device__ int g_col[NET];
__device__ int g_bsum[NB5];
__device__ int g_boff[NB5];
__device__ int g_tick;             // ZERO at entry
__device__ int g_flag;             // ZERO at entry
__device__ float g_h[(size_t)NN * 135];
__device__ float g_o[(size_t)NN * 135];
__device__ float g_xagg[(size_t)NN * 27];
__device__ float g_W2p[KP * WPAD];
__device__ float g_als3[NN];
__device__ float g_ald3[NN];
__device__ float4 g_als[NN];
__device__ float4 g_ald[NN];
__device__ unsigned g_pool[NGR * 4];  // ZERO at entry (0 < enc(-inf), acts as -infinity)
__device__ int g_nz;

__device__ __forceinline__ unsigned enc(float f) {
    unsigned u = __float_as_uint(f);
    return (u & 0x80000000u) ? ~u : (u | 0x80000000u);
}
__device__ __forceinline__ float dec(unsigned u) {
    return __uint_as_float((u & 0x80000000u) ? (u ^ 0x80000000u) : ~u);
}
__device__ __forceinline__ long long ld_idx(const void* p, long long i, bool is64) {
    if (is64) return ((const long long*)p)[i];
    return (long long)((const int*)p)[i];
}

// ---------------- 1: sniff dtype + pad W2 + rowptr[NN] ----------------
__global__ void k_pre(const int* ei32, const float* __restrict__ W2) {
    int i = blockIdx.x * blockDim.x + threadIdx.x;
    if (i < KP * WPAD) {
        int k = i / WPAD, c = i - k * WPAD;
        g_W2p[i] = (k < 135 && c < 54) ? W2[k * 54 + c] : 0.f;
    }
    if (i == 0) g_rowptr[NN] = NET;
    if (blockIdx.x == 0 && threadIdx.x < 32) {
        int lane = threadIdx.x;
        int nz = 0;
        for (int j = lane; j < 512; j += 32)
            if (ei32[2 * j + 1] != 0) nz++;
        #pragma unroll
        for (int o = 16; o; o >>= 1) nz += __shfl_xor_sync(0xffffffffu, nz, o);
        if (lane == 0) g_nz = nz;   // 0 => int64
    }
}

// ---------------- 2: degree count (g_deg zero at entry; self-loop added in scan) ----------------
__global__ void k_count(const void* ei) {
    int e = blockIdx.x * blockDim.x + threadIdx.x;
    if (e >= NE) return;
    bool is64 = (g_nz == 0);
    int dst = (int)ld_idx(ei, (long long)NE + e, is64);
    atomicAdd(&g_deg[dst], 1);
}

// ---------------- 3: layer-1 logits from x (fused v-vector precompute) ----------------
__global__ void k_alpha_x(const float* __restrict__ x, const float* __restrict__ W1,
                          const float* __restrict__ a_src, const float* __restrict__ a_dst) {
    __shared__ float v[2][3][9];
    int t = threadIdx.x;
    if (t < 54) {
        int side = t / 27, r = t % 27;
        int h = r / 9, k = r % 9;
        const float* a = side ? a_dst : a_src;
        float s = 0.f;
        for (int c = 0; c < 45; c++)
            s += __ldg(&W1[k * 135 + h * 45 + c]) * __ldg(&a[h * 45 + c]);
        v[side][h][k] = s;
    }
    __syncthreads();
    int n = blockIdx.x * blockDim.x + t;
    if (n >= NN) return;
    float xv[9];
    #pragma unroll
    for (int k = 0; k < 9; k++) xv[k] = x[(size_t)n * 9 + k];
    float s[3], d[3];
    #pragma unroll
    for (int h = 0; h < 3; h++) {
        float ss = 0.f, dd = 0.f;
        #pragma unroll
        for (int k = 0; k < 9; k++) {
            ss += xv[k] * v[0][h][k];
            dd += xv[k] * v[1][h][k];
        }
        s[h] = ss; d[h] = dd;
    }
    g_als[n] = make_float4(s[0], s[1], s[2], 0.f);
    g_ald[n] = make_float4(d[0], d[1], d[2], 0.f);
}

// ---------------- 4: single-pass exclusive scan of (deg+1) -> rowptr/cursor ----------------
// 157 blocks x 512 threads: all resident (80k threads), ticket + flag-spin is deadlock-free
__global__ void k_scanall() {
    __shared__ int sm[512];
    __shared__ int s_last;
    __shared__ int s_off;
    int b = blockIdx.x, t = threadIdx.x;
    int i = b * 512 + t;
    int v = (i < NN) ? g_deg[i] + 1 : 0;   // +1 = self loop
    sm[t] = v;
    __syncthreads();
    #pragma unroll
    for (int off = 1; off < 512; off <<= 1) {
        int u = (t >= off) ? sm[t - off] : 0;
        __syncthreads();
        sm[t] += u;
        __syncthreads();
    }
    int incl = sm[t];
    int total = sm[511];
    __syncthreads();
    if (t == 0) {
        g_bsum[b] = total;
        __threadfence();
        int tk = atomicAdd(&g_tick, 1);
        s_last = (tk == NB5 - 1);
    }
    __syncthreads();
    if (s_last) {
        int u = (t < NB5) ? g_bsum[t] : 0;
        sm[t] = u;
        __syncthreads();
        #pragma unroll
        for (int off = 1; off < 512; off <<= 1) {
            int w = (t >= off) ? sm[t - off] : 0;
            __syncthreads();
            sm[t] += w;
            __syncthreads();
        }
        if (t < NB5) g_boff[t] = sm[t] - u;   // exclusive
        __threadfence();
        if (t == 0) atomicExch(&g_flag, 1);
    } else {
        if (t == 0) {
            while (atomicAdd(&g_flag, 0) == 0) __nanosleep(64);
        }
    }
    __syncthreads();
    if (t == 0) s_off = atomicAdd(&g_boff[b], 0);   // L1-bypassing read
    __syncthreads();
    if (i < NN) {
        int p = s_off + incl - v;
        g_rowptr[i] = p;
        g_cursor[i] = p;
    }
}

// ---------------- 5: CSR fill ----------------
__global__ void k_fill(const void* ei) {
    int e = blockIdx.x * blockDim.x + threadIdx.x;
    if (e >= NET) return;
    bool is64 = (g_nz == 0);
    int s, d;
    if (e < NE) {
        s = (int)ld_idx(ei, e, is64);
        d = (int)ld_idx(ei, (long long)NE + e, is64);
    } else {
        s = d = e - NE;
    }
    int pos = atomicAdd(&g_cursor[d], 1);
    g_col[pos] = s;
}

// ---------------- 6: layer-1 aggregation of raw x (27 accumulators), warp/node ----------------
__global__ void k_aggx(const float* __restrict__ x) {
    int wid = (blockIdx.x * blockDim.x + threadIdx.x) >> 5;
    if (wid >= NN) return;
    int lane = threadIdx.x & 31;
    int n = wid;
    int hh = lane / 9, cc = lane - hh * 9;
    bool act = lane < 27;
    int beg = g_rowptr[n], end = g_rowptr[n + 1];
    float4 ald4 = g_ald[n];
    float aldv[3] = { ald4.x, ald4.y, ald4.z };
    float acc = 0.f;
    float ssum[3] = { 0.f, 0.f, 0.f };

    for (int base = beg; base < end; base += 32) {
        int cnt = min(32, end - base);
        int s_l = 0;
        float e_l[3] = { 0.f, 0.f, 0.f };
        if (lane < cnt) {
            s_l = g_col[base + lane];
            float4 a = g_als[s_l];
            float av[3] = { a.x, a.y, a.z };
            #pragma unroll
            for (int h = 0; h < 3; h++) {
                float al = av[h] + aldv[h];
                al = (al > 0.f) ? al : 0.2f * al;
                e_l[h] = __expf(fminf(al, 80.f));
            }
        }
        #pragma unroll
        for (int h = 0; h < 3; h++) ssum[h] += e_l[h];

        int jj = 0;
        for (; jj + 4 <= cnt; jj += 4) {
            int s0 = __shfl_sync(0xffffffffu, s_l, jj + 0);
            int s1 = __shfl_sync(0xffffffffu, s_l, jj + 1);
            int s2 = __shfl_sync(0xffffffffu, s_l, jj + 2);
            int s3 = __shfl_sync(0xffffffffu, s_l, jj + 3);
            float w0a = __shfl_sync(0xffffffffu, e_l[0], jj + 0);
            float w0b = __shfl_sync(0xffffffffu, e_l[1], jj + 0);
            float w0c = __shfl_sync(0xffffffffu, e_l[2], jj + 0);
            float w1a = __shfl_sync(0xffffffffu, e_l[0], jj + 1);
            float w1b = __shfl_sync(0xffffffffu, e_l[1], jj + 1);
            float w1c = __shfl_sync(0xffffffffu, e_l[2], jj + 1);
            float w2a = __shfl_sync(0xffffffffu, e_l[0], jj + 2);
            float w2b = __shfl_sync(0xffffffffu, e_l[1], jj + 2);
            float w2c = __shfl_sync(0xffffffffu, e_l[2], jj + 2);
            float w3a = __shfl_sync(0xffffffffu, e_l[0], jj + 3);
            float w3b = __shfl_sync(0xffffffffu, e_l[1], jj + 3);
            float w3c = __shfl_sync(0xffffffffu, e_l[2], jj + 3);
            if (act) {
                float x0 = __ldg(&x[(size_t)s0 * 9 + cc]);
                float x1 = __ldg(&x[(size_t)s1 * 9 + cc]);
                float x2 = __ldg(&x[(size_t)s2 * 9 + cc]);
                float x3 = __ldg(&x[(size_t)s3 * 9 + cc]);
                float wa = (hh == 0) ? w0a : (hh == 1) ? w0b : w0c;
                float wb = (hh == 0) ? w1a : (hh == 1) ? w1b : w1c;
                float wc = (hh == 0) ? w2a : (hh == 1) ? w2b : w2c;
                float wd = (hh == 0) ? w3a : (hh == 1) ? w3b : w3c;
                acc += wa * x0;
                acc += wb * x1;
                acc += wc * x2;
                acc += wd * x3;
            }
        }
        for (; jj < cnt; jj++) {
            int s = __shfl_sync(0xffffffffu, s_l, jj);
            float wa0 = __shfl_sync(0xffffffffu, e_l[0], jj);
            float wa1 = __shfl_sync(0xffffffffu, e_l[1], jj);
            float wa2 = __shfl_sync(0xffffffffu, e_l[2], jj);
            if (act) {
                float xv = __ldg(&x[(size_t)s * 9 + cc]);
                float w = (hh == 0) ? wa0 : (hh == 1) ? wa1 : wa2;
                acc += w * xv;
            }
        }
    }
    #pragma unroll
    for (int h = 0; h < 3; h++)
        #pragma unroll
        for (int o = 16; o; o >>= 1)
            ssum[h] += __shfl_xor_sync(0xffffffffu, ssum[h], o);
    if (act)
        g_xagg[(size_t)n * 27 + lane] = acc / (ssum[hh] + 1e-16f);
}

// ---------------- 7: fused map1 + gemm2 + alpha2 epilogue ----------------
// reads xagg (27/node), computes o1 tile (64x135) in smem, then 135->54 GEMM
__global__ void k_gemm2f(const float* __restrict__ W1, const float* __restrict__ b1,
                         float* __restrict__ Y,
                         const float* __restrict__ a_src, const float* __restrict__ a_dst) {
    constexpr int NPB = 64;
    __shared__ __align__(16) float xs[NPB * KP];
    __shared__ float xa[NPB * 28];
    int tid = threadIdx.x;
    int nodeBase = blockIdx.x * NPB;
    // stage xagg tile
    for (int i = tid; i < NPB * 27; i += 256) {
        int r = i / 27, c = i - r * 27;
        xa[r * 28 + c] = g_xagg[(size_t)(nodeBase + r) * 27 + c];
    }
    __syncthreads();
    // compute o1 tile = relu(xagg @ W1slice + b1) into xs
    for (int i = tid; i < NPB * KP; i += 256) {
        int r = i / KP, c = i - r * KP;
        float o = 0.f;
        if (c < 135) {
            int h = c / 45;
            const float* ap = xa + r * 28 + h * 9;
            float s = 0.f;
            #pragma unroll
            for (int k = 0; k < 9; k++)
                s += ap[k] * __ldg(&W1[k * 135 + c]);
            o = fmaxf(s + __ldg(&b1[c]), 0.f);
        }
        xs[i] = o;
    }
    __syncthreads();
    int ng = tid / 16, j = tid & 15;
    int c0 = j * 4;
    float acc[4][4];
    #pragma unroll
    for (int q = 0; q < 4; q++)
        #pragma unroll
        for (int m = 0; m < 4; m++) acc[q][m] = 0.f;
    const float* xp = xs + (ng * 4) * KP;
    for (int k4 = 0; k4 < KP / 4; k4++) {
        float xr0[4], xr1[4], xr2[4], xr3[4];
        *(float4*)xr0 = *(const float4*)&xp[k4 * 4];
        *(float4*)xr1 = *(const float4*)&xp[KP + k4 * 4];
        *(float4*)xr2 = *(const float4*)&xp[2 * KP + k4 * 4];
        *(float4*)xr3 = *(const float4*)&xp[3 * KP + k4 * 4];
        #pragma unroll
        for (int kk = 0; kk < 4; kk++) {
            float wr[4];
            *(float4*)wr = __ldg((const float4*)&g_W2p[(k4 * 4 + kk) * WPAD + c0]);
            #pragma unroll
            for (int m = 0; m < 4; m++) {
                acc[0][m] += xr0[kk] * wr[m];
                acc[1][m] += xr1[kk] * wr[m];
                acc[2][m] += xr2[kk] * wr[m];
                acc[3][m] += xr3[kk] * wr[m];
            }
        }
    }
    float as_c[4], ad_c[4];
    #pragma unroll
    for (int m = 0; m < 4; m++) {
        int c = c0 + m;
        as_c[m] = (c < 54) ? __ldg(&a_src[c]) : 0.f;
        ad_c[m] = (c < 54) ? __ldg(&a_dst[c]) : 0.f;
    }
    #pragma unroll
    for (int q = 0; q < 4; q++) {
        int n = nodeBase + ng * 4 + q;
        float ps0 = 0.f, ps1 = 0.f, ps2 = 0.f;
        float pd0 = 0.f, pd1 = 0.f, pd2 = 0.f;
        #pragma unroll
        for (int m = 0; m < 4; m++) {
            int c = c0 + m;
            if (c < 54) {
                Y[(size_t)n * 54 + c] = acc[q][m];
                int h = c / 18;
                float vs = acc[q][m] * as_c[m];
                float vd = acc[q][m] * ad_c[m];
                if (h == 0) { ps0 += vs; pd0 += vd; }
                else if (h == 1) { ps1 += vs; pd1 += vd; }
                else { ps2 += vs; pd2 += vd; }
            }
        }
        #pragma unroll
        for (int o = 8; o; o >>= 1) {
            ps0 += __shfl_xor_sync(0xffffffffu, ps0, o);
            ps1 += __shfl_xor_sync(0xffffffffu, ps1, o);
            ps2 += __shfl_xor_sync(0xffffffffu, ps2, o);
            pd0 += __shfl_xor_sync(0xffffffffu, pd0, o);
            pd1 += __shfl_xor_sync(0xffffffffu, pd1, o);
            pd2 += __shfl_xor_sync(0xffffffffu, pd2, o);
        }
        if (j == 0) {
            g_als[n] = make_float4(ps0, ps1, ps2, 0.f);
            g_ald[n] = make_float4(pd0, pd1, pd2, 0.f);
        }
    }
}

// ---------------- 8: agg2 + fused gemm3 + layer-3 logits ----------------
__global__ void k_agg2(const float* __restrict__ hfeat,
                       const float* __restrict__ bias,
                       const float* __restrict__ W3,
                       const float* __restrict__ as3, const float* __restrict__ ad3,
                       float* __restrict__ h3out) {
    int wid = (blockIdx.x * blockDim.x + threadIdx.x) >> 5;
    if (wid >= NN) return;
    int lane = threadIdx.x & 31;
    int n = wid;
    bool act = lane < 27;
    int c0 = 2 * lane;
    int hd = lane / 9;
    int beg = g_rowptr[n], end = g_rowptr[n + 1];
    float4 ald4 = g_ald[n];
    float aldv[3] = { ald4.x, ald4.y, ald4.z };
    float2 acc = make_float2(0.f, 0.f);
    float ssum0 = 0.f, ssum1 = 0.f, ssum2 = 0.f;

    for (int base = beg; base < end; base += 32) {
        int cnt = min(32, end - base);
        int s_l = 0;
        float e_l[3] = { 0.f, 0.f, 0.f };
        if (lane < cnt) {
            s_l = g_col[base + lane];
            float4 a = g_als[s_l];
            float av[3] = { a.x, a.y, a.z };
            #pragma unroll
            for (int h = 0; h < 3; h++) {
                float al = av[h] + aldv[h];
                al = (al > 0.f) ? al : 0.2f * al;
                e_l[h] = __expf(fminf(al, 80.f));
            }
        }
        ssum0 += e_l[0]; ssum1 += e_l[1]; ssum2 += e_l[2];

        int jj = 0;
        for (; jj + 4 <= cnt; jj += 4) {
            int s0 = __shfl_sync(0xffffffffu, s_l, jj + 0);
            int s1 = __shfl_sync(0xffffffffu, s_l, jj + 1);
            int s2 = __shfl_sync(0xffffffffu, s_l, jj + 2);
            int s3 = __shfl_sync(0xffffffffu, s_l, jj + 3);
            float w0a = __shfl_sync(0xffffffffu, e_l[0], jj + 0);
            float w0b = __shfl_sync(0xffffffffu, e_l[1], jj + 0);
            float w0c = __shfl_sync(0xffffffffu, e_l[2], jj + 0);
            float w1a = __shfl_sync(0xffffffffu, e_l[0], jj + 1);
            float w1b = __shfl_sync(0xffffffffu, e_l[1], jj + 1);
            float w1c = __shfl_sync(0xffffffffu, e_l[2], jj + 1);
            float w2a = __shfl_sync(0xffffffffu, e_l[0], jj + 2);
            float w2b = __shfl_sync(0xffffffffu, e_l[1], jj + 2);
            float w2c = __shfl_sync(0xffffffffu, e_l[2], jj + 2);
            float w3a = __shfl_sync(0xffffffffu, e_l[0], jj + 3);
            float w3b = __shfl_sync(0xffffffffu, e_l[1], jj + 3);
            float w3c = __shfl_sync(0xffffffffu, e_l[2], jj + 3);
            if (act) {
                float2 g0 = *(const float2*)&hfeat[(size_t)s0 * 54 + c0];
                float2 g1 = *(const float2*)&hfeat[(size_t)s1 * 54 + c0];
                float2 g2 = *(const float2*)&hfeat[(size_t)s2 * 54 + c0];
                float2 g3 = *(const float2*)&hfeat[(size_t)s3 * 54 + c0];
                float wa = (hd == 0) ? w0a : (hd == 1) ? w0b : w0c;
                float wb = (hd == 0) ? w1a : (hd == 1) ? w1b : w1c;
                float wc = (hd == 0) ? w2a : (hd == 1) ? w2b : w2c;
                float wd = (hd == 0) ? w3a : (hd == 1) ? w3b : w3c;
                acc.x += wa * g0.x; acc.y += wa * g0.y;
                acc.x += wb * g1.x; acc.y += wb * g1.y;
                acc.x += wc * g2.x; acc.y += wc * g2.y;
                acc.x += wd * g3.x; acc.y += wd * g3.y;
            }
        }
        for (; jj < cnt; jj++) {
            int s = __shfl_sync(0xffffffffu, s_l, jj);
            float wa0 = __shfl_sync(0xffffffffu, e_l[0], jj);
            float wa1 = __shfl_sync(0xffffffffu, e_l[1], jj);
            float wa2 = __shfl_sync(0xffffffffu, e_l[2], jj);
            if (act) {
                float2 g = *(const float2*)&hfeat[(size_t)s * 54 + c0];
                float w = (hd == 0) ? wa0 : (hd == 1) ? wa1 : wa2;
                acc.x += w * g.x; acc.y += w * g.y;
            }
        }
    }
    #pragma unroll
    for (int o = 16; o; o >>= 1) {
        ssum0 += __shfl_xor_sync(0xffffffffu, ssum0, o);
        ssum1 += __shfl_xor_sync(0xffffffffu, ssum1, o);
        ssum2 += __shfl_xor_sync(0xffffffffu, ssum2, o);
    }
    float2 o2 = make_float2(0.f, 0.f);
    if (act) {
        float ss = (hd == 0) ? ssum0 : (hd == 1) ? ssum1 : ssum2;
        float inv = 1.f / (ss + 1e-16f);
        o2.x = fmaxf(acc.x * inv + __ldg(&bias[c0]), 0.f);
        o2.y = fmaxf(acc.y * inv + __ldg(&bias[c0 + 1]), 0.f);
    }
    float t0 = 0.f, t1 = 0.f, t2 = 0.f, t3 = 0.f;
    if (act) {
        float4 wr0 = __ldg((const float4*)&W3[c0 * 4]);
        float4 wr1 = __ldg((const float4*)&W3[(c0 + 1) * 4]);
        t0 = o2.x * wr0.x + o2.y * wr1.x;
        t1 = o2.x * wr0.y + o2.y * wr1.y;
        t2 = o2.x * wr0.z + o2.y * wr1.z;
        t3 = o2.x * wr0.w + o2.y * wr1.w;
    }
    #pragma unroll
    for (int o = 16; o; o >>= 1) {
        t0 += __shfl_xor_sync(0xffffffffu, t0, o);
        t1 += __shfl_xor_sync(0xffffffffu, t1, o);
        t2 += __shfl_xor_sync(0xffffffffu, t2, o);
        t3 += __shfl_xor_sync(0xffffffffu, t3, o);
    }
    if (lane == 0) {
        *(float4*)&h3out[(size_t)n * 4] = make_float4(t0, t1, t2, t3);
        g_als3[n] = t0 * __ldg(&as3[0]) + t1 * __ldg(&as3[1]) + t2 * __ldg(&as3[2]) + t3 * __ldg(&as3[3]);
        g_ald3[n] = t0 * __ldg(&ad3[0]) + t1 * __ldg(&ad3[1]) + t2 * __ldg(&ad3[2]) + t3 * __ldg(&ad3[3]);
    }
}

// ---------------- 9: layer-3 agg + global max pool ----------------
__global__ void k_agg3(const float* __restrict__ hfeat,
                       const float* __restrict__ bias,
                       const void* __restrict__ batch) {
    int wid = (blockIdx.x * blockDim.x + threadIdx.x) >> 5;
    if (wid >= NN) return;
    int lane = threadIdx.x & 31;
    int sub = lane >> 2, c = lane & 3;
    int n = wid;
    int beg = g_rowptr[n], end = g_rowptr[n + 1];
    float aldn = g_ald3[n];
    float acc = 0.f, wsum = 0.f;
    for (int e0 = beg; e0 < end; e0 += 8) {
        int e = e0 + sub;
        if (e < end) {
            int s = g_col[e];
            float al = g_als3[s] + aldn;
            al = (al > 0.f) ? al : 0.2f * al;
            float w = __expf(fminf(al, 80.f));
            acc += w * __ldg(&hfeat[(size_t)s * 4 + c]);
            wsum += w;
        }
    }
    #pragma unroll
    for (int o = 4; o < 32; o <<= 1) {
        acc += __shfl_xor_sync(0xffffffffu, acc, o);
        wsum += __shfl_xor_sync(0xffffffffu, wsum, o);
    }
    if (lane < 4) {
        float o = acc / (wsum + 1e-16f) + __ldg(&bias[lane]);
        bool is64 = (g_nz == 0);
        int g = (int)ld_idx(batch, n, is64);
        atomicMax(&g_pool[g * 4 + lane], enc(o));
    }
}

// ---------------- 10: log-softmax + restore clean state ----------------
__global__ void k_final(float* __restrict__ out) {
    int b = blockIdx.x, t = threadIdx.x;
    if (b == 0) {
        float v[4];
        #pragma unroll
        for (int c = 0; c < 4; c++) {
            unsigned u = g_pool[t * 4 + c];
            v[c] = (u <= 0x007FFFFFu) ? -1e9f : dec(u);   // 0-start or -inf -> guard
        }
        float m = fmaxf(fmaxf(v[0], v[1]), fmaxf(v[2], v[3]));
        float s = 0.f;
        #pragma unroll
        for (int c = 0; c < 4; c++) s += expf(v[c] - m);
        float lse = m + logf(s);
        #pragma unroll
        for (int c = 0; c < 4; c++) out[t * 4 + c] = v[c] - lse;
        __syncthreads();
        #pragma unroll
        for (int c = 0; c < 4; c++) g_pool[t * 4 + c] = 0u;   // restore
    }
    if (b == 1 && t == 0) { g_tick = 0; g_flag = 0; }         // restore
    int i = b * 256 + t;
    if (i < NN) g_deg[i] = 0;                                 // restore
}

// ---------------- launch ----------------
extern "C" void kernel_launch(void* const* d_in, const int* in_sizes, int n_in,
                              void* d_out, int out_size) {
    const float* x   = (const float*)d_in[0];
    const void*  ei  = d_in[1];
    const void*  bat = d_in[2];
    const float* W1  = (const float*)d_in[3];
    const float* as1 = (const float*)d_in[4];
    const float* ad1 = (const float*)d_in[5];
    const float* b1  = (const float*)d_in[6];
    const float* W2  = (const float*)d_in[7];
    const float* as2 = (const float*)d_in[8];
    const float* ad2 = (const float*)d_in[9];
    const float* b2  = (const float*)d_in[10];
    const float* W3  = (const float*)d_in[11];
    const float* as3 = (const float*)d_in[12];
    const float* ad3 = (const float*)d_in[13];
    const float* b3  = (const float*)d_in[14];
    float* out = (float*)d_out;

    float *hbuf, *obuf;
    cudaGetSymbolAddress((void**)&hbuf, g_h);
    cudaGetSymbolAddress((void**)&obuf, g_o);

    k_pre<<<30, 256>>>((const int*)ei, W2);                  // 1
    k_count<<<(NE + 255) / 256, 256>>>(ei);                  // 2
    k_alpha_x<<<(NN + 255) / 256, 256>>>(x, W1, as1, ad1);   // 3
    k_scanall<<<NB5, 512>>>();                               // 4 (profiled)
    k_fill<<<(NET + 255) / 256, 256>>>(ei);                  // 5
    k_aggx<<<NN / 8, 256>>>(x);                              // 6
    k_gemm2f<<<NN / 64, 256>>>(W1, b1, hbuf, as2, ad2);      // 7
    k_agg2<<<NN / 8, 256>>>(hbuf, b2, W3, as3, ad3, obuf);   // 8
    k_agg3<<<NN / 8, 256>>>(obuf, b3, bat);                  // 9
    k_final<<<(NN + 255) / 256, 256>>>(out);                 // 10
}